// round 2
// baseline (speedup 1.0000x reference)
#include <cuda_runtime.h>
#include <cuda_bf16.h>

// ANFIS fuzzy inference, batch=2M rows x 4 features.
// Per row: 11 Gaussian memberships mu_i = exp(-0.5*((x[dim]-c)/sigma)^2),
// 30 rules w_j = prod of 4 mus, out = sum(w*conseq_clip)/max(sum(w),1e-8).
//
// Rule antecedents form a subset of {0,1,2}x{3,4,5}x{6,7,8}x{9,10}; we CSE
// the 9 front-pair products P and 6 back-pair products Q so each rule is a
// single multiply.

namespace {
// Rule tables (compile-time; fully unrolled so indices fold to constants)
__device__ constexpr int RA0[30] = {0,0,0,0,0,0,1,0,1,0,0,1,1,1,0,0,1,1,2,0,1,2,2,2,2,1,2,1,2,1};
__device__ constexpr int RA1[30] = {3,3,3,4,3,4,3,5,3,3,4,4,3,3,5,4,4,3,3,5,5,4,5,5,4,5,5,5,4,4};
__device__ constexpr int RA2[30] = {8,8,7,8,7,8,8,8,8,6,7,7,7,6,7,6,8,7,7,6,7,8,6,6,6,6,7,6,6,6};
__device__ constexpr int RA3[30] = {9,10,9,9,10,10,9,9,10,9,10,9,10,9,10,9,10,9,9,9,9,9,10,9,10,10,10,9,9,10};
__device__ constexpr int DM[11]  = {0,0,0,1,1,1,2,2,2,3,3};
}

constexpr int THREADS = 256;
constexpr int ROWS_PER_THREAD = 4;
constexpr int TILE = THREADS * ROWS_PER_THREAD;   // 1024 rows per block

__device__ __forceinline__ float anfis_row(const float4 xv,
                                           const float* __restrict__ a,
                                           const float* __restrict__ b,
                                           const float* __restrict__ cq)
{
    const float xd[4] = {xv.x, xv.y, xv.z, xv.w};

    // 11 Gaussian memberships
    float mu[11];
    #pragma unroll
    for (int i = 0; i < 11; i++) {
        float d = fmaf(xd[DM[i]], a[i], b[i]);
        mu[i] = __expf(-0.5f * d * d);
    }

    // Pair products (CSE of the 4-way rule products)
    float P[3][3];   // mu[0..2] * mu[3..5]
    #pragma unroll
    for (int i = 0; i < 3; i++)
        #pragma unroll
        for (int j = 0; j < 3; j++)
            P[i][j] = mu[i] * mu[3 + j];
    float Q[3][2];   // mu[6..8] * mu[9..10]
    #pragma unroll
    for (int i = 0; i < 3; i++)
        #pragma unroll
        for (int j = 0; j < 2; j++)
            Q[i][j] = mu[6 + i] * mu[9 + j];

    // 30 rules: one MUL + ADD + FMA each
    float wsum = 0.0f, acc = 0.0f;
    #pragma unroll
    for (int j = 0; j < 30; j++) {
        float w = P[RA0[j]][RA1[j] - 3] * Q[RA2[j] - 6][RA3[j] - 9];
        wsum += w;
        acc   = fmaf(w, cq[j], acc);
    }

    return __fdividef(acc, fmaxf(wsum, 1e-8f));
}

__global__ void __launch_bounds__(THREADS)
anfis_kernel(const float4* __restrict__ x,
             const float*  __restrict__ c,
             const float*  __restrict__ log_s,
             const float*  __restrict__ conseq,
             float* __restrict__ out,
             int n)
{
    // Per-block precomputed constants:
    //   s_a[i]  = 1/sigma_i
    //   s_b[i]  = -c_i/sigma_i      (so d = fma(x, a, b))
    //   s_cq[j] = clip(conseq_j, 0, 100)
    __shared__ float s_a[11], s_b[11], s_cq[30];

    const int t = threadIdx.x;
    if (t < 11) {
        float ci  = __ldg(c + t);
        float sg  = fmaxf(__expf(__ldg(log_s + t)), 0.001f);
        float inv = 1.0f / sg;
        s_a[t] = inv;
        s_b[t] = -ci * inv;
    }
    if (t < 30) {
        s_cq[t] = fminf(fmaxf(__ldg(conseq + t), 0.0f), 100.0f);
    }
    __syncthreads();

    float a[11], b[11], cq[30];
    #pragma unroll
    for (int i = 0; i < 11; i++) { a[i] = s_a[i]; b[i] = s_b[i]; }
    #pragma unroll
    for (int j = 0; j < 30; j++) { cq[j] = s_cq[j]; }

    const int base = blockIdx.x * TILE + t;

    if (blockIdx.x * TILE + TILE <= n) {
        // Full tile: no predication, 4 back-to-back LDG.128 (MLP=4).
        float4 xv[ROWS_PER_THREAD];
        #pragma unroll
        for (int k = 0; k < ROWS_PER_THREAD; k++)
            xv[k] = __ldg(x + base + k * THREADS);

        float res[ROWS_PER_THREAD];
        #pragma unroll
        for (int k = 0; k < ROWS_PER_THREAD; k++)
            res[k] = anfis_row(xv[k], a, b, cq);

        #pragma unroll
        for (int k = 0; k < ROWS_PER_THREAD; k++)
            out[base + k * THREADS] = res[k];
    } else {
        // Tail tile: predicated.
        #pragma unroll
        for (int k = 0; k < ROWS_PER_THREAD; k++) {
            int r = base + k * THREADS;
            if (r < n) {
                float4 xv = __ldg(x + r);
                out[r] = anfis_row(xv, a, b, cq);
            }
        }
    }
}

extern "C" void kernel_launch(void* const* d_in, const int* in_sizes, int n_in,
                              void* d_out, int out_size)
{
    const float* x      = (const float*)d_in[0];
    const float* c      = (const float*)d_in[1];
    const float* log_s  = (const float*)d_in[2];
    const float* conseq = (const float*)d_in[3];
    float* out          = (float*)d_out;

    int n = in_sizes[0] / 4;   // number of rows
    int blocks = (n + TILE - 1) / TILE;

    anfis_kernel<<<blocks, THREADS>>>((const float4*)x, c, log_s, conseq, out, n);
}